// round 6
// baseline (speedup 1.0000x reference)
#include <cuda_runtime.h>
#include <cuda_bf16.h>

#define BB 64
#define TT 512
#define DD 1024
#define F4 (DD / 4)          // 256 float4 per row
#define TSEG 64              // rows per segment
#define NSEG (TT / TSEG)     // 8 segments
#define NTHREADS 256

// Scratch (allocation-free). Partial sums per (b, seg): [BB*NSEG][F4]
__device__ float4       g_ps[BB * NSEG * F4];
__device__ float4       g_py[BB * NSEG * F4];
__device__ unsigned int g_cnt[BB];   // zero-init; reset by epilogue each replay

__global__ __launch_bounds__(NTHREADS) void fused_kernel(
    const float* __restrict__ vseq,     // [B,T,D]
    const int*   __restrict__ slen,     // [B]
    const int*   __restrict__ words,    // [B,T]
    const float* __restrict__ weights,  // [VOCAB]
    float*       __restrict__ out)      // [2,B,D]: y then y_hat
{
    const int b   = blockIdx.x;
    const int seg = blockIdx.y;
    const int tid = threadIdx.x;        // = float4 column 0..255
    const int L   = slen[b];

    const int t0   = seg * TSEG;
    const int tend = min(L, t0 + TSEG);
    const int n    = tend - t0;         // rows this block processes (may be <=0)

    __shared__ float w_sh[TSEG];

    if (n > 0) {
        // Gather per-token weights for this segment only
        if (tid < n) w_sh[tid] = __ldg(&weights[words[b * TT + t0 + tid]]);
        __syncthreads();

        const float4* p = (const float4*)vseq + ((size_t)b * TT + t0) * F4 + tid;

        float4 s  = make_float4(0.f, 0.f, 0.f, 0.f);
        float4 yh = make_float4(0.f, 0.f, 0.f, 0.f);

        int t = 0;
        // 8-deep batched loads: 8 independent LDG.128 in flight before use
        for (; t + 8 <= n; t += 8) {
            float4 v0 = __ldcs(p + (size_t)(t + 0) * F4);
            float4 v1 = __ldcs(p + (size_t)(t + 1) * F4);
            float4 v2 = __ldcs(p + (size_t)(t + 2) * F4);
            float4 v3 = __ldcs(p + (size_t)(t + 3) * F4);
            float4 v4 = __ldcs(p + (size_t)(t + 4) * F4);
            float4 v5 = __ldcs(p + (size_t)(t + 5) * F4);
            float4 v6 = __ldcs(p + (size_t)(t + 6) * F4);
            float4 v7 = __ldcs(p + (size_t)(t + 7) * F4);
            float w0 = w_sh[t + 0], w1 = w_sh[t + 1];
            float w2 = w_sh[t + 2], w3 = w_sh[t + 3];
            float w4 = w_sh[t + 4], w5 = w_sh[t + 5];
            float w6 = w_sh[t + 6], w7 = w_sh[t + 7];
            s.x += v0.x; s.y += v0.y; s.z += v0.z; s.w += v0.w;
            yh.x += v0.x * w0; yh.y += v0.y * w0; yh.z += v0.z * w0; yh.w += v0.w * w0;
            s.x += v1.x; s.y += v1.y; s.z += v1.z; s.w += v1.w;
            yh.x += v1.x * w1; yh.y += v1.y * w1; yh.z += v1.z * w1; yh.w += v1.w * w1;
            s.x += v2.x; s.y += v2.y; s.z += v2.z; s.w += v2.w;
            yh.x += v2.x * w2; yh.y += v2.y * w2; yh.z += v2.z * w2; yh.w += v2.w * w2;
            s.x += v3.x; s.y += v3.y; s.z += v3.z; s.w += v3.w;
            yh.x += v3.x * w3; yh.y += v3.y * w3; yh.z += v3.z * w3; yh.w += v3.w * w3;
            s.x += v4.x; s.y += v4.y; s.z += v4.z; s.w += v4.w;
            yh.x += v4.x * w4; yh.y += v4.y * w4; yh.z += v4.z * w4; yh.w += v4.w * w4;
            s.x += v5.x; s.y += v5.y; s.z += v5.z; s.w += v5.w;
            yh.x += v5.x * w5; yh.y += v5.y * w5; yh.z += v5.z * w5; yh.w += v5.w * w5;
            s.x += v6.x; s.y += v6.y; s.z += v6.z; s.w += v6.w;
            yh.x += v6.x * w6; yh.y += v6.y * w6; yh.z += v6.z * w6; yh.w += v6.w * w6;
            s.x += v7.x; s.y += v7.y; s.z += v7.z; s.w += v7.w;
            yh.x += v7.x * w7; yh.y += v7.y * w7; yh.z += v7.z * w7; yh.w += v7.w * w7;
        }
        for (; t < n; t++) {
            float4 v = __ldcs(p + (size_t)t * F4);
            float  w = w_sh[t];
            s.x += v.x; s.y += v.y; s.z += v.z; s.w += v.w;
            yh.x += v.x * w; yh.y += v.y * w; yh.z += v.z * w; yh.w += v.w * w;
        }

        // Publish this segment's partials
        const size_t slot = ((size_t)b * NSEG + seg) * F4 + tid;
        g_ps[slot] = s;
        g_py[slot] = yh;
    }

    // Signal arrival; last block of this batch does the reduction epilogue
    __threadfence();
    __shared__ int isLast;
    if (tid == 0) {
        unsigned int arrived = atomicAdd(&g_cnt[b], 1u);
        isLast = (arrived == NSEG - 1) ? 1 : 0;
    }
    __syncthreads();

    if (isLast) {
        const int nact = (L + TSEG - 1) / TSEG;   // active segments, >=1

        float4 S = make_float4(0.f, 0.f, 0.f, 0.f);
        float4 Y = make_float4(0.f, 0.f, 0.f, 0.f);
        #pragma unroll
        for (int sg = 0; sg < NSEG; sg++) {
            if (sg < nact) {
                const size_t slot = ((size_t)b * NSEG + sg) * F4 + tid;
                float4 a = __ldcg(&g_ps[slot]);
                float4 h = __ldcg(&g_py[slot]);
                S.x += a.x; S.y += a.y; S.z += a.z; S.w += a.w;
                Y.x += h.x; Y.y += h.y; Y.z += h.z; Y.w += h.w;
            }
        }

        // Block-wide deterministic reduction of sum(|S|) over all 1024 cols
        float a = fabsf(S.x) + fabsf(S.y) + fabsf(S.z) + fabsf(S.w);
        #pragma unroll
        for (int off = 16; off > 0; off >>= 1)
            a += __shfl_down_sync(0xffffffffu, a, off);

        __shared__ float wsum[NTHREADS / 32];
        __shared__ float nrm_sh;
        if ((tid & 31) == 0) wsum[tid >> 5] = a;
        __syncthreads();
        if (tid == 0) {
            float tot = 0.f;
            #pragma unroll
            for (int i = 0; i < NTHREADS / 32; i++) tot += wsum[i];
            nrm_sh = rsqrtf(tot);
            g_cnt[b] = 0u;                    // reset for next graph replay
        }
        __syncthreads();
        const float rinv = nrm_sh;

        float4* yp  = (float4*)out + (size_t)b * F4;               // y
        float4* yhp = (float4*)out + (size_t)(BB + b) * F4;        // y_hat
        S.x *= rinv; S.y *= rinv; S.z *= rinv; S.w *= rinv;
        yp[tid]  = S;
        yhp[tid] = Y;
    }
}

extern "C" void kernel_launch(void* const* d_in, const int* in_sizes, int n_in,
                              void* d_out, int out_size) {
    const float* vseq    = (const float*)d_in[0];   // [B,T,D] fp32
    const int*   slen    = (const int*)  d_in[1];   // [B] int32
    const int*   words   = (const int*)  d_in[2];   // [B,T] int32
    const float* weights = (const float*)d_in[3];   // [VOCAB] fp32
    float*       out     = (float*)d_out;           // [2*B*D] fp32: y, y_hat

    dim3 grid(BB, NSEG);
    fused_kernel<<<grid, NTHREADS>>>(vseq, slen, words, weights, out);
}

// round 8
// speedup vs baseline: 1.0272x; 1.0272x over previous
#include <cuda_runtime.h>
#include <cuda_bf16.h>

#define BB 64
#define TT 512
#define DD 1024
#define F4 (DD / 4)          // 256 float4 per row
#define CQ 32                // rows per work item (chunk)
#define MAXCH (TT / CQ)      // 16 chunks per batch max
#define NTHREADS 256
#define GRID 592             // 148 SMs x 4 blocks -> uniform single wave

// Scratch (allocation-free). Partials per (b, chunk): 2 x 4 MB, L2-resident.
__device__ float4       g_ps[BB * MAXCH * F4];
__device__ float4       g_py[BB * MAXCH * F4];
__device__ unsigned int g_cnt[BB];   // zero-init; reset by epilogue each replay

__global__ __launch_bounds__(NTHREADS) void fused_kernel(
    const float* __restrict__ vseq,     // [B,T,D]
    const int*   __restrict__ slen,     // [B]
    const int*   __restrict__ words,    // [B,T]
    const float* __restrict__ weights,  // [VOCAB]
    float*       __restrict__ out)      // [2,B,D]: y then y_hat
{
    const int tid = threadIdx.x;        // = float4 column 0..255

    __shared__ int len_sh[BB];
    __shared__ int pfx[BB + 1];
    if (tid < BB) len_sh[tid] = slen[tid];
    __syncthreads();
    if (tid == 0) {
        int acc = 0;
        pfx[0] = 0;
        #pragma unroll 8
        for (int i = 0; i < BB; i++) {
            acc += (len_sh[i] + CQ - 1) / CQ;
            pfx[i + 1] = acc;
        }
    }
    __syncthreads();
    const int C = pfx[BB];              // total work items

    __shared__ float w_sh[CQ];
    __shared__ int   flag;

    for (int item = blockIdx.x; item < C; item += GRID) {
        // largest b with pfx[b] <= item (uniform across block)
        int lo = 0, hi = BB;
        while (hi - lo > 1) {
            int mid = (lo + hi) >> 1;
            if (pfx[mid] <= item) lo = mid; else hi = mid;
        }
        const int b  = lo;
        const int c  = item - pfx[b];
        const int L  = len_sh[b];
        const int t0 = c * CQ;
        const int n  = min(L - t0, CQ);   // >= 1 by construction

        __syncthreads();                  // protect w_sh reuse across items
        if (tid < n) w_sh[tid] = __ldg(&weights[words[b * TT + t0 + tid]]);
        __syncthreads();

        const float4* p = (const float4*)vseq + ((size_t)b * TT + t0) * F4 + tid;

        float4 s  = make_float4(0.f, 0.f, 0.f, 0.f);
        float4 yh = make_float4(0.f, 0.f, 0.f, 0.f);

        int t = 0;
        for (; t + 8 <= n; t += 8) {      // 8 independent LDG.128 in flight
            float4 v0 = __ldcs(p + (size_t)(t + 0) * F4);
            float4 v1 = __ldcs(p + (size_t)(t + 1) * F4);
            float4 v2 = __ldcs(p + (size_t)(t + 2) * F4);
            float4 v3 = __ldcs(p + (size_t)(t + 3) * F4);
            float4 v4 = __ldcs(p + (size_t)(t + 4) * F4);
            float4 v5 = __ldcs(p + (size_t)(t + 5) * F4);
            float4 v6 = __ldcs(p + (size_t)(t + 6) * F4);
            float4 v7 = __ldcs(p + (size_t)(t + 7) * F4);
            float w0 = w_sh[t + 0], w1 = w_sh[t + 1];
            float w2 = w_sh[t + 2], w3 = w_sh[t + 3];
            float w4 = w_sh[t + 4], w5 = w_sh[t + 5];
            float w6 = w_sh[t + 6], w7 = w_sh[t + 7];
            s.x += v0.x; s.y += v0.y; s.z += v0.z; s.w += v0.w;
            yh.x += v0.x * w0; yh.y += v0.y * w0; yh.z += v0.z * w0; yh.w += v0.w * w0;
            s.x += v1.x; s.y += v1.y; s.z += v1.z; s.w += v1.w;
            yh.x += v1.x * w1; yh.y += v1.y * w1; yh.z += v1.z * w1; yh.w += v1.w * w1;
            s.x += v2.x; s.y += v2.y; s.z += v2.z; s.w += v2.w;
            yh.x += v2.x * w2; yh.y += v2.y * w2; yh.z += v2.z * w2; yh.w += v2.w * w2;
            s.x += v3.x; s.y += v3.y; s.z += v3.z; s.w += v3.w;
            yh.x += v3.x * w3; yh.y += v3.y * w3; yh.z += v3.z * w3; yh.w += v3.w * w3;
            s.x += v4.x; s.y += v4.y; s.z += v4.z; s.w += v4.w;
            yh.x += v4.x * w4; yh.y += v4.y * w4; yh.z += v4.z * w4; yh.w += v4.w * w4;
            s.x += v5.x; s.y += v5.y; s.z += v5.z; s.w += v5.w;
            yh.x += v5.x * w5; yh.y += v5.y * w5; yh.z += v5.z * w5; yh.w += v5.w * w5;
            s.x += v6.x; s.y += v6.y; s.z += v6.z; s.w += v6.w;
            yh.x += v6.x * w6; yh.y += v6.y * w6; yh.z += v6.z * w6; yh.w += v6.w * w6;
            s.x += v7.x; s.y += v7.y; s.z += v7.z; s.w += v7.w;
            yh.x += v7.x * w7; yh.y += v7.y * w7; yh.z += v7.z * w7; yh.w += v7.w * w7;
        }
        for (; t < n; t++) {
            float4 v = __ldcs(p + (size_t)t * F4);
            float  w = w_sh[t];
            s.x += v.x; s.y += v.y; s.z += v.z; s.w += v.w;
            yh.x += v.x * w; yh.y += v.y * w; yh.z += v.z * w; yh.w += v.w * w;
        }

        const size_t slot = ((size_t)b * MAXCH + c) * F4 + tid;
        g_ps[slot] = s;                   // default store -> L2 write-back
        g_py[slot] = yh;

        __threadfence();                  // publish partials (release)
        if (tid == 0) {
            const int nact = pfx[b + 1] - pfx[b];
            unsigned int arrived = atomicAdd(&g_cnt[b], 1u);
            flag = (arrived == (unsigned)(nact - 1)) ? 1 : 0;
        }
        __syncthreads();

        if (flag) {
            __threadfence();              // acquire side
            const int nact = pfx[b + 1] - pfx[b];

            float4 S = make_float4(0.f, 0.f, 0.f, 0.f);
            float4 Y = make_float4(0.f, 0.f, 0.f, 0.f);
            for (int sg = 0; sg < nact; sg++) {
                const size_t sl = ((size_t)b * MAXCH + sg) * F4 + tid;
                float4 a = __ldcg(&g_ps[sl]);
                float4 h = __ldcg(&g_py[sl]);
                S.x += a.x; S.y += a.y; S.z += a.z; S.w += a.w;
                Y.x += h.x; Y.y += h.y; Y.z += h.z; Y.w += h.w;
            }

            // deterministic block-wide sum of |S| over all 1024 columns
            float a = fabsf(S.x) + fabsf(S.y) + fabsf(S.z) + fabsf(S.w);
            #pragma unroll
            for (int off = 16; off > 0; off >>= 1)
                a += __shfl_down_sync(0xffffffffu, a, off);

            __shared__ float wsum[NTHREADS / 32];
            __shared__ float rinv_sh;
            if ((tid & 31) == 0) wsum[tid >> 5] = a;
            __syncthreads();
            if (tid == 0) {
                float tot = 0.f;
                #pragma unroll
                for (int i = 0; i < NTHREADS / 32; i++) tot += wsum[i];
                rinv_sh = rsqrtf(tot);
                g_cnt[b] = 0u;            // reset for next graph replay
            }
            __syncthreads();
            const float rinv = rinv_sh;

            float4* yp  = (float4*)out + (size_t)b * F4;          // y
            float4* yhp = (float4*)out + (size_t)(BB + b) * F4;   // y_hat
            S.x *= rinv; S.y *= rinv; S.z *= rinv; S.w *= rinv;
            yp[tid]  = S;
            yhp[tid] = Y;
        }
    }
}

extern "C" void kernel_launch(void* const* d_in, const int* in_sizes, int n_in,
                              void* d_out, int out_size) {
    const float* vseq    = (const float*)d_in[0];   // [B,T,D] fp32
    const int*   slen    = (const int*)  d_in[1];   // [B] int32
    const int*   words   = (const int*)  d_in[2];   // [B,T] int32
    const float* weights = (const float*)d_in[3];   // [VOCAB] fp32
    float*       out     = (float*)d_out;           // [2*B*D] fp32: y, y_hat

    fused_kernel<<<GRID, NTHREADS>>>(vseq, slen, words, weights, out);
}